// round 1
// baseline (speedup 1.0000x reference)
#include <cuda_runtime.h>
#include <cuda_bf16.h>
#include <cstdint>

#define N_NODES 50000
#define N_EDGES 800000

// ---------------- scratch (device globals; no allocation allowed) ----------
__device__ int   g_is64;
__device__ int   g_cnt[N_NODES];
__device__ int   g_fill[N_NODES];
__device__ int   g_rowptr[N_NODES + 1];
__device__ int   g_col[N_EDGES];
__device__ float g_w[N_EDGES];
__device__ float g_dinv[N_NODES];
__device__ float g_H[(size_t)N_NODES * 128];   // GEMM output
__device__ float g_A[(size_t)N_NODES * 128];   // aggregation output

// ---------------- edge-index dtype sniffing --------------------------------
// jax.random.randint(dtype=int64) silently downgrades to int32 when x64 is
// disabled. Values are < 50000, so reading int32 data as int64 words yields
// values >= 2^32 with overwhelming probability. Detect once per launch.
__global__ void k_detect(const void* ei) {
    const unsigned long long* p = (const unsigned long long*)ei;
    int ok64 = 1;
    for (int k = 0; k < 16; k++)
        if (p[k] >= (unsigned long long)N_NODES) ok64 = 0;
    g_is64 = ok64;
}

__device__ __forceinline__ int load_idx(const void* ei, long long pos) {
    if (g_is64) return (int)((const long long*)ei)[pos];
    return ((const int*)ei)[pos];
}

// ---------------- preprocessing ---------------------------------------------
__global__ void k_zero() {
    int i = blockIdx.x * blockDim.x + threadIdx.x;
    if (i < N_NODES) { g_cnt[i] = 0; g_fill[i] = 0; }
}

__global__ void k_hist(const void* ei) {
    int e = blockIdx.x * blockDim.x + threadIdx.x;
    if (e < N_EDGES) {
        int d = load_idx(ei, (long long)N_EDGES + e);
        atomicAdd(&g_cnt[d], 1);
    }
}

__global__ void k_dinv() {
    int i = blockIdx.x * blockDim.x + threadIdx.x;
    if (i < N_NODES) g_dinv[i] = rsqrtf((float)(g_cnt[i] + 1)); // +1 self loop
}

// single-block exclusive scan of g_cnt -> g_rowptr (50k elements)
__global__ void k_scan() {
    __shared__ int sh[1024];
    __shared__ int s_carry;
    int t = threadIdx.x;
    if (t == 0) s_carry = 0;
    __syncthreads();
    for (int base = 0; base < N_NODES; base += 1024) {
        int v = (base + t < N_NODES) ? g_cnt[base + t] : 0;
        sh[t] = v;
        __syncthreads();
        for (int off = 1; off < 1024; off <<= 1) {
            int add = (t >= off) ? sh[t - off] : 0;
            __syncthreads();
            sh[t] += add;
            __syncthreads();
        }
        int carry = s_carry;
        if (base + t < N_NODES) g_rowptr[base + t] = carry + sh[t] - v;
        __syncthreads();
        if (t == 0) s_carry = carry + sh[1023];
        __syncthreads();
    }
    if (threadIdx.x == 0) g_rowptr[N_NODES] = s_carry;
}

__global__ void k_fill(const void* ei) {
    int e = blockIdx.x * blockDim.x + threadIdx.x;
    if (e < N_EDGES) {
        int s = load_idx(ei, e);
        int d = load_idx(ei, (long long)N_EDGES + e);
        int pos = g_rowptr[d] + atomicAdd(&g_fill[d], 1);
        g_col[pos] = s;
        g_w[pos]   = g_dinv[s] * g_dinv[d];
    }
}

// ---------------- dense GEMM: Y[N,NO] = X[N,K] @ W[K,NO] -------------------
// blockDim = NO. W lives in smem; ROWS rows of X staged in smem per block.
template <int K, int NO, int ROWS>
__global__ void k_gemm(const float* __restrict__ X, const float* __restrict__ W,
                       float* __restrict__ Y) {
    extern __shared__ float sm[];
    float* Wsh = sm;             // K*NO
    float* Xsh = sm + K * NO;    // ROWS*K
    int t = threadIdx.x;
    for (int i = t; i < K * NO; i += NO) Wsh[i] = W[i];
    size_t r0 = (size_t)blockIdx.x * ROWS;
    for (int i = t; i < ROWS * K; i += NO) Xsh[i] = X[r0 * K + i];
    __syncthreads();
#pragma unroll
    for (int r = 0; r < ROWS; r += 4) {
        float a0 = 0.f, a1 = 0.f, a2 = 0.f, a3 = 0.f;
#pragma unroll 16
        for (int k = 0; k < K; k++) {
            float wv = Wsh[k * NO + t];
            a0 = fmaf(Xsh[(r + 0) * K + k], wv, a0);
            a1 = fmaf(Xsh[(r + 1) * K + k], wv, a1);
            a2 = fmaf(Xsh[(r + 2) * K + k], wv, a2);
            a3 = fmaf(Xsh[(r + 3) * K + k], wv, a3);
        }
        Y[(r0 + r + 0) * NO + t] = a0;
        Y[(r0 + r + 1) * NO + t] = a1;
        Y[(r0 + r + 2) * NO + t] = a2;
        Y[(r0 + r + 3) * NO + t] = a3;
    }
}

// ---------------- sparse aggregation: one warp per node --------------------
// out[i] = (relu?)( sum_{e: dst=i} w_e * H[src_e] + dinv[i]^2 * H[i] + b )
template <int F, bool RELU>
__global__ void k_agg(const float* __restrict__ H, const float* __restrict__ b,
                      float* __restrict__ out) {
    int gw   = (blockIdx.x * blockDim.x + threadIdx.x) >> 5;
    int lane = threadIdx.x & 31;
    if (gw >= N_NODES) return;
    int s = g_rowptr[gw], e = g_rowptr[gw + 1];

    if constexpr (F == 128) {
        float4 acc = make_float4(0.f, 0.f, 0.f, 0.f);
        for (int j = s; j < e; j++) {
            int   c = g_col[j];
            float w = g_w[j];
            float4 h = ((const float4*)(H + (size_t)c * 128))[lane];
            acc.x = fmaf(w, h.x, acc.x);
            acc.y = fmaf(w, h.y, acc.y);
            acc.z = fmaf(w, h.z, acc.z);
            acc.w = fmaf(w, h.w, acc.w);
        }
        float di = g_dinv[gw];
        float wl = di * di;
        float4 hs = ((const float4*)(H + (size_t)gw * 128))[lane];
        acc.x = fmaf(wl, hs.x, acc.x);
        acc.y = fmaf(wl, hs.y, acc.y);
        acc.z = fmaf(wl, hs.z, acc.z);
        acc.w = fmaf(wl, hs.w, acc.w);
        float4 bb = ((const float4*)b)[lane];
        acc.x += bb.x; acc.y += bb.y; acc.z += bb.z; acc.w += bb.w;
        if (RELU) {
            acc.x = fmaxf(acc.x, 0.f); acc.y = fmaxf(acc.y, 0.f);
            acc.z = fmaxf(acc.z, 0.f); acc.w = fmaxf(acc.w, 0.f);
        }
        ((float4*)(out + (size_t)gw * 128))[lane] = acc;
    } else { // F == 64
        float2 acc = make_float2(0.f, 0.f);
        for (int j = s; j < e; j++) {
            int   c = g_col[j];
            float w = g_w[j];
            float2 h = ((const float2*)(H + (size_t)c * 64))[lane];
            acc.x = fmaf(w, h.x, acc.x);
            acc.y = fmaf(w, h.y, acc.y);
        }
        float di = g_dinv[gw];
        float wl = di * di;
        float2 hs = ((const float2*)(H + (size_t)gw * 64))[lane];
        acc.x = fmaf(wl, hs.x, acc.x);
        acc.y = fmaf(wl, hs.y, acc.y);
        float2 bb = ((const float2*)b)[lane];
        acc.x += bb.x; acc.y += bb.y;
        if (RELU) { acc.x = fmaxf(acc.x, 0.f); acc.y = fmaxf(acc.y, 0.f); }
        ((float2*)(out + (size_t)gw * 64))[lane] = acc;
    }
}

// ---------------- launch ----------------------------------------------------
extern "C" void kernel_launch(void* const* d_in, const int* in_sizes, int n_in,
                              void* d_out, int out_size) {
    const float* x  = (const float*)d_in[0];
    const void*  ei = d_in[1];
    const float* W1 = (const float*)d_in[2];
    const float* b1 = (const float*)d_in[3];
    const float* W2 = (const float*)d_in[4];
    const float* b2 = (const float*)d_in[5];
    const float* W3 = (const float*)d_in[6];
    const float* b3 = (const float*)d_in[7];
    float* out = (float*)d_out;

    // smem budgets (bytes): gemm1 needs > 48KB default
    constexpr int SM1 = (128 * 128 + 8 * 128) * 4;   // 69632
    constexpr int SM2 = (128 * 64 + 16 * 128) * 4;   // 40960
    constexpr int SM3 = (64 * 128 + 8 * 64) * 4;     // 34816
    cudaFuncSetAttribute(k_gemm<128, 128, 8>,
                         cudaFuncAttributeMaxDynamicSharedMemorySize, SM1);
    cudaFuncSetAttribute(k_gemm<128, 64, 16>,
                         cudaFuncAttributeMaxDynamicSharedMemorySize, SM2);
    cudaFuncSetAttribute(k_gemm<64, 128, 8>,
                         cudaFuncAttributeMaxDynamicSharedMemorySize, SM3);

    void *pH = nullptr, *pA = nullptr;
    cudaGetSymbolAddress(&pH, g_H);
    cudaGetSymbolAddress(&pA, g_A);
    float* H = (float*)pH;
    float* A = (float*)pA;

    const int TB = 256;
    int gN = (N_NODES + TB - 1) / TB;
    int gE = (N_EDGES + TB - 1) / TB;

    // preprocessing: degree norm + CSR(dst)
    k_detect<<<1, 1>>>(ei);
    k_zero<<<gN, TB>>>();
    k_hist<<<gE, TB>>>(ei);
    k_dinv<<<gN, TB>>>();
    k_scan<<<1, 1024>>>();
    k_fill<<<gE, TB>>>(ei);

    int aggBlocks = (N_NODES * 32 + TB - 1) / TB;

    // layer 1: 128 -> 128, relu
    k_gemm<128, 128, 8><<<N_NODES / 8, 128, SM1>>>(x, W1, H);
    k_agg<128, true><<<aggBlocks, TB>>>(H, b1, A);
    // layer 2: 128 -> 64, relu
    k_gemm<128, 64, 16><<<N_NODES / 16, 64, SM2>>>(A, W2, H);
    k_agg<64, true><<<aggBlocks, TB>>>(H, b2, A);
    // layer 3: 64 -> 128, no relu, straight to output
    k_gemm<64, 128, 8><<<N_NODES / 8, 128, SM3>>>(A, W3, H);
    k_agg<128, false><<<aggBlocks, TB>>>(H, b3, out);
}

// round 2
// speedup vs baseline: 1.1479x; 1.1479x over previous
#include <cuda_runtime.h>
#include <cuda_bf16.h>
#include <cstdint>

#define N_NODES 50000
#define N_EDGES 800000

// ---------------- scratch (device globals; no allocation allowed) ----------
__device__ int   g_is64;
__device__ int   g_cnt[N_NODES];
__device__ int   g_fill[N_NODES];
__device__ int   g_rowptr[N_NODES + 1];
__device__ int2  g_cw[N_EDGES];               // (src, weight-bits) interleaved
__device__ float g_dinv[N_NODES];
__device__ float g_H[(size_t)N_NODES * 128];  // GEMM / agg ping
__device__ float g_A[(size_t)N_NODES * 128];  // GEMM / agg pong

// ---------------- edge-index dtype sniffing --------------------------------
// jax.random.randint(dtype=int64) silently downgrades to int32 when x64 is
// disabled. Values are < 50000, so int32 data read as int64 words yields
// values >= 2^32 with overwhelming probability.
__device__ __forceinline__ int load_idx(const void* ei, long long pos) {
    if (g_is64) return (int)((const long long*)ei)[pos];
    return ((const int*)ei)[pos];
}

// ---------------- preprocessing ---------------------------------------------
__global__ void k_zero(const void* ei) {
    int i = blockIdx.x * blockDim.x + threadIdx.x;
    if (i < N_NODES) g_cnt[i] = 0;
    if (i == 0) {
        const unsigned long long* p = (const unsigned long long*)ei;
        int ok = 1;
        for (int k = 0; k < 16; k++)
            if (p[k] >= (unsigned long long)N_NODES) ok = 0;
        g_is64 = ok;
    }
}

__global__ void k_hist(const void* ei) {
    int e = blockIdx.x * blockDim.x + threadIdx.x;
    if (e < N_EDGES) {
        int d = load_idx(ei, (long long)N_EDGES + e);
        atomicAdd(&g_cnt[d], 1);
    }
}

// single block: serial-chunk scan + dinv + fill-zero + rowptr[N]
__global__ void k_scan() {
    __shared__ int sh[1024];
    int t = threadIdx.x;
    int base = t * 49;
    int end = min(base + 49, N_NODES);
    int sum = 0;
    for (int i = base; i < end; i++) sum += g_cnt[i];
    sh[t] = sum;
    __syncthreads();
    for (int off = 1; off < 1024; off <<= 1) {
        int v = (t >= off) ? sh[t - off] : 0;
        __syncthreads();
        sh[t] += v;
        __syncthreads();
    }
    int run = (t > 0) ? sh[t - 1] : 0;
    for (int i = base; i < end; i++) {
        int c = g_cnt[i];
        g_rowptr[i] = run;
        run += c;
        g_fill[i] = 0;
        g_dinv[i] = rsqrtf((float)(c + 1));   // +1 self loop
    }
    if (t == 1023) g_rowptr[N_NODES] = run;
}

__global__ void k_fill(const void* ei) {
    int e = blockIdx.x * blockDim.x + threadIdx.x;
    if (e < N_EDGES) {
        int s = load_idx(ei, e);
        int d = load_idx(ei, (long long)N_EDGES + e);
        int pos = g_rowptr[d] + atomicAdd(&g_fill[d], 1);
        float w = g_dinv[s] * g_dinv[d];
        g_cw[pos] = make_int2(s, __float_as_int(w));
    }
}

// ---------------- dense GEMM: Y[N,NO] = X[N,K] @ W[K,NO] (+bias) ----------
// 16 rows/block, NO threads. Thread computes 4 strided cols x 4 rows using
// packed fp32x2 FMA (exact fp32 math, 2x FFMA throughput on sm_103a).
template <int K, int NO, bool BIAS>
__global__ void k_gemm(const float* __restrict__ X, const float* __restrict__ W,
                       const float* __restrict__ bias, float* __restrict__ Y) {
    constexpr int RB = 16;
    constexpr int XS = RB + 2;      // padded stride for transposed X tile
    extern __shared__ float sm[];
    float* Wsh = sm;                // K*NO
    float* Xsh = sm + K * NO;       // K*XS, Xsh[k*XS + r]
    int tid = threadIdx.x;

    const float4* W4 = (const float4*)W;
    float4* Wsh4 = (float4*)Wsh;
#pragma unroll
    for (int i = tid; i < K * NO / 4; i += NO) Wsh4[i] = W4[i];

    size_t r0 = (size_t)blockIdx.x * RB;
#pragma unroll
    for (int i = tid; i < RB * K; i += NO) {
        int r = i / K, k = i & (K - 1);
        Xsh[k * XS + r] = X[(r0 + r) * K + k];
    }
    __syncthreads();

    int ry = tid & 3;               // rows 4*ry .. 4*ry+3
    int cx = tid >> 2;              // cols cx + q*(NO/4)
    unsigned long long acc[4][2];
#pragma unroll
    for (int q = 0; q < 4; q++) { acc[q][0] = 0ull; acc[q][1] = 0ull; }

#pragma unroll 8
    for (int k = 0; k < K; k++) {
        unsigned long long x0 = *(const unsigned long long*)(Xsh + k * XS + 4 * ry);
        unsigned long long x1 = *(const unsigned long long*)(Xsh + k * XS + 4 * ry + 2);
#pragma unroll
        for (int q = 0; q < 4; q++) {
            float w = Wsh[k * NO + cx + q * (NO / 4)];
            unsigned long long wd;
            asm("mov.b64 %0, {%1, %1};" : "=l"(wd) : "f"(w));
            asm("fma.rn.f32x2 %0, %1, %2, %0;" : "+l"(acc[q][0]) : "l"(x0), "l"(wd));
            asm("fma.rn.f32x2 %0, %1, %2, %0;" : "+l"(acc[q][1]) : "l"(x1), "l"(wd));
        }
    }

#pragma unroll
    for (int q = 0; q < 4; q++) {
        int c = cx + q * (NO / 4);
        float bv = BIAS ? bias[c] : 0.0f;
#pragma unroll
        for (int p = 0; p < 2; p++) {
            float lo = __uint_as_float((unsigned)acc[q][p]);
            float hi = __uint_as_float((unsigned)(acc[q][p] >> 32));
            int r = 4 * ry + 2 * p;
            Y[(r0 + r) * NO + c]     = lo + bv;
            Y[(r0 + r + 1) * NO + c] = hi + bv;
        }
    }
}

// ---------------- sparse aggregation: one warp per node --------------------
// out[i] = (relu?)( sum_{e: dst=i} w_e * H[src_e] + dinv[i]^2 * H[i] (+ b) )
template <int F, bool RELU, bool BIAS>
__global__ void k_agg(const float* __restrict__ H, const float* __restrict__ b,
                      float* __restrict__ out) {
    int gw   = (blockIdx.x * blockDim.x + threadIdx.x) >> 5;
    int lane = threadIdx.x & 31;
    if (gw >= N_NODES) return;
    int s = g_rowptr[gw], e = g_rowptr[gw + 1];

    if constexpr (F == 128) {
        float4 acc = make_float4(0.f, 0.f, 0.f, 0.f);
#pragma unroll 4
        for (int j = s; j < e; j++) {
            int2 cw = __ldg(&g_cw[j]);
            float w = __int_as_float(cw.y);
            float4 h = __ldg(((const float4*)(H + (size_t)cw.x * 128)) + lane);
            acc.x = fmaf(w, h.x, acc.x);
            acc.y = fmaf(w, h.y, acc.y);
            acc.z = fmaf(w, h.z, acc.z);
            acc.w = fmaf(w, h.w, acc.w);
        }
        float di = g_dinv[gw];
        float wl = di * di;
        float4 hs = ((const float4*)(H + (size_t)gw * 128))[lane];
        acc.x = fmaf(wl, hs.x, acc.x);
        acc.y = fmaf(wl, hs.y, acc.y);
        acc.z = fmaf(wl, hs.z, acc.z);
        acc.w = fmaf(wl, hs.w, acc.w);
        if (BIAS) {
            float4 bb = ((const float4*)b)[lane];
            acc.x += bb.x; acc.y += bb.y; acc.z += bb.z; acc.w += bb.w;
        }
        if (RELU) {
            acc.x = fmaxf(acc.x, 0.f); acc.y = fmaxf(acc.y, 0.f);
            acc.z = fmaxf(acc.z, 0.f); acc.w = fmaxf(acc.w, 0.f);
        }
        ((float4*)(out + (size_t)gw * 128))[lane] = acc;
    } else { // F == 64
        float2 acc = make_float2(0.f, 0.f);
#pragma unroll 4
        for (int j = s; j < e; j++) {
            int2 cw = __ldg(&g_cw[j]);
            float w = __int_as_float(cw.y);
            float2 h = __ldg(((const float2*)(H + (size_t)cw.x * 64)) + lane);
            acc.x = fmaf(w, h.x, acc.x);
            acc.y = fmaf(w, h.y, acc.y);
        }
        float di = g_dinv[gw];
        float wl = di * di;
        float2 hs = ((const float2*)(H + (size_t)gw * 64))[lane];
        acc.x = fmaf(wl, hs.x, acc.x);
        acc.y = fmaf(wl, hs.y, acc.y);
        if (BIAS) {
            float2 bb = ((const float2*)b)[lane];
            acc.x += bb.x; acc.y += bb.y;
        }
        if (RELU) { acc.x = fmaxf(acc.x, 0.f); acc.y = fmaxf(acc.y, 0.f); }
        ((float2*)(out + (size_t)gw * 64))[lane] = acc;
    }
}

// ---------------- launch ----------------------------------------------------
extern "C" void kernel_launch(void* const* d_in, const int* in_sizes, int n_in,
                              void* d_out, int out_size) {
    const float* x  = (const float*)d_in[0];
    const void*  ei = d_in[1];
    const float* W1 = (const float*)d_in[2];
    const float* b1 = (const float*)d_in[3];
    const float* W2 = (const float*)d_in[4];
    const float* b2 = (const float*)d_in[5];
    const float* W3 = (const float*)d_in[6];
    const float* b3 = (const float*)d_in[7];
    float* out = (float*)d_out;

    constexpr int SM1 = (128 * 128 + 128 * 18) * 4;  // 74752
    constexpr int SM2 = (128 * 64 + 128 * 18) * 4;   // 41984
    constexpr int SM3 = (64 * 128 + 64 * 18) * 4;    // 37376
    cudaFuncSetAttribute(k_gemm<128, 128, false>,
                         cudaFuncAttributeMaxDynamicSharedMemorySize, SM1);
    cudaFuncSetAttribute(k_gemm<128, 64, false>,
                         cudaFuncAttributeMaxDynamicSharedMemorySize, SM2);
    cudaFuncSetAttribute(k_gemm<64, 128, true>,
                         cudaFuncAttributeMaxDynamicSharedMemorySize, SM3);

    void *pH = nullptr, *pA = nullptr;
    cudaGetSymbolAddress(&pH, g_H);
    cudaGetSymbolAddress(&pA, g_A);
    float* H = (float*)pH;
    float* A = (float*)pA;

    const int TB = 256;
    int gN = (N_NODES + TB - 1) / TB;
    int gE = (N_EDGES + TB - 1) / TB;
    int aggBlocks = (N_NODES * 32 + TB - 1) / TB;

    // preprocessing: degree norm + CSR(dst)
    k_zero<<<gN, TB>>>(ei);
    k_hist<<<gE, TB>>>(ei);
    k_scan<<<1, 1024>>>();
    k_fill<<<gE, TB>>>(ei);

    // layer 1: relu(agg(x@W1) + b1)
    k_gemm<128, 128, false><<<N_NODES / 16, 128, SM1>>>(x, W1, nullptr, H);
    k_agg<128, true, true><<<aggBlocks, TB>>>(H, b1, A);
    // layer 2: relu(agg(h@W2) + b2)
    k_gemm<128, 64, false><<<N_NODES / 16, 64, SM2>>>(A, W2, nullptr, H);
    k_agg<64, true, true><<<aggBlocks, TB>>>(H, b2, A);
    // layer 3 (reordered, agg is linear): out = agg(h) @ W3 + b3
    k_agg<64, false, false><<<aggBlocks, TB>>>(A, nullptr, H);
    k_gemm<64, 128, true><<<N_NODES / 16, 128, SM3>>>(H, W3, b3, out);
}

// round 3
// speedup vs baseline: 1.5187x; 1.3230x over previous
#include <cuda_runtime.h>
#include <cuda_bf16.h>
#include <cstdint>

#define N_NODES 50000
#define N_EDGES 800000

// ---------------- scratch (device globals; no allocation allowed) ----------
__device__ int   g_is64;
__device__ int   g_cnt[N_NODES];
__device__ int   g_fill[N_NODES];
__device__ int   g_rowptr[N_NODES + 1];
__device__ int2  g_cw[N_EDGES];               // (src, weight-bits) interleaved
__device__ float g_dinv[N_NODES];
__device__ float g_H[(size_t)N_NODES * 128];  // GEMM / agg ping
__device__ float g_A[(size_t)N_NODES * 128];  // GEMM / agg pong

// ---------------- edge-index dtype sniffing --------------------------------
__device__ __forceinline__ int load_idx(const void* ei, long long pos) {
    if (g_is64) return (int)((const long long*)ei)[pos];
    return ((const int*)ei)[pos];
}

// ---------------- preprocessing ---------------------------------------------
__global__ void k_zero(const void* ei) {
    int i = blockIdx.x * blockDim.x + threadIdx.x;
    if (i < N_NODES) g_cnt[i] = 0;
    if (i == 0) {
        const unsigned long long* p = (const unsigned long long*)ei;
        int ok = 1;
        for (int k = 0; k < 16; k++)
            if (p[k] >= (unsigned long long)N_NODES) ok = 0;
        g_is64 = ok;
    }
}

__global__ void k_hist(const void* ei) {
    int e = blockIdx.x * blockDim.x + threadIdx.x;
    if (e < N_EDGES) {
        int d = load_idx(ei, (long long)N_EDGES + e);
        atomicAdd(&g_cnt[d], 1);
    }
}

// single block: serial-chunk scan + dinv + fill-zero + rowptr[N]
__global__ void k_scan() {
    __shared__ int sh[1024];
    int t = threadIdx.x;
    int base = t * 49;
    int end = min(base + 49, N_NODES);
    int sum = 0;
    for (int i = base; i < end; i++) sum += g_cnt[i];
    sh[t] = sum;
    __syncthreads();
    for (int off = 1; off < 1024; off <<= 1) {
        int v = (t >= off) ? sh[t - off] : 0;
        __syncthreads();
        sh[t] += v;
        __syncthreads();
    }
    int run = (t > 0) ? sh[t - 1] : 0;
    for (int i = base; i < end; i++) {
        int c = g_cnt[i];
        g_rowptr[i] = run;
        run += c;
        g_fill[i] = 0;
        g_dinv[i] = rsqrtf((float)(c + 1));   // +1 self loop
    }
    if (t == 1023) g_rowptr[N_NODES] = run;
}

__global__ void k_fill(const void* ei) {
    int e = blockIdx.x * blockDim.x + threadIdx.x;
    if (e < N_EDGES) {
        int s = load_idx(ei, e);
        int d = load_idx(ei, (long long)N_EDGES + e);
        int pos = g_rowptr[d] + atomicAdd(&g_fill[d], 1);
        float w = g_dinv[s] * g_dinv[d];
        g_cw[pos] = make_int2(s, __float_as_int(w));
    }
}

// ---------------- dense GEMM: Y[N,NO] = X[N,K] @ W[K,NO] (+bias) ----------
// Block: 256 threads, tile RB x NO with RB*NO = 8192 (RB=64 for NO=128,
// RB=128 for NO=64). K staged in chunks of 32. Each thread: 4 rows x 8 cols,
// columns packed in pairs for fp32x2 FMA loaded directly from contiguous Wsh.
template <int K, int NO, bool BIAS>
__global__ void __launch_bounds__(256) k_gemm(const float* __restrict__ X,
                                              const float* __restrict__ W,
                                              const float* __restrict__ bias,
                                              float* __restrict__ Y) {
    constexpr int RB = 8192 / NO;          // 64 or 128
    constexpr int KC = 32;
    constexpr int XS = RB + 4;             // transposed-X stride (mult of 4)
    __shared__ float Wsh[KC * NO];
    __shared__ float Xsh[KC * XS];

    int tid = threadIdx.x;
    int rg = tid & (RB / 4 - 1);           // row group: rows 4*rg..4*rg+3
    int cg = tid / (RB / 4);               // col group: cols 8*cg..8*cg+7
    long long r0 = (long long)blockIdx.x * RB;

    unsigned long long acc[4][4];
#pragma unroll
    for (int r = 0; r < 4; r++)
#pragma unroll
        for (int c = 0; c < 4; c++) acc[r][c] = 0ull;

    for (int kc = 0; kc < K; kc += KC) {
        __syncthreads();
        // stage W chunk [KC x NO]
        const float4* W4 = (const float4*)(W + kc * NO);
        float4* Wsh4 = (float4*)Wsh;
#pragma unroll
        for (int i = tid; i < KC * NO / 4; i += 256) Wsh4[i] = W4[i];
        // stage X chunk transposed: Xsh[k*XS + r] = X[(r0+r)*K + kc + k]
#pragma unroll
        for (int i = tid; i < RB * KC; i += 256) {
            int r = i >> 5, k = i & 31;
            long long row = r0 + r;
            if (row >= N_NODES) row = 0;   // clamp; store is guarded
            Xsh[k * XS + r] = X[row * K + kc + k];
        }
        __syncthreads();

#pragma unroll 8
        for (int k = 0; k < KC; k++) {
            float4 xv = *(const float4*)(Xsh + k * XS + 4 * rg);
            unsigned long long xd[4];
            asm("mov.b64 %0, {%1, %1};" : "=l"(xd[0]) : "f"(xv.x));
            asm("mov.b64 %0, {%1, %1};" : "=l"(xd[1]) : "f"(xv.y));
            asm("mov.b64 %0, {%1, %1};" : "=l"(xd[2]) : "f"(xv.z));
            asm("mov.b64 %0, {%1, %1};" : "=l"(xd[3]) : "f"(xv.w));
            const unsigned long long* wp =
                (const unsigned long long*)(Wsh + k * NO + 8 * cg);
            unsigned long long w0 = wp[0], w1 = wp[1], w2 = wp[2], w3 = wp[3];
#pragma unroll
            for (int r = 0; r < 4; r++) {
                asm("fma.rn.f32x2 %0, %1, %2, %0;" : "+l"(acc[r][0]) : "l"(xd[r]), "l"(w0));
                asm("fma.rn.f32x2 %0, %1, %2, %0;" : "+l"(acc[r][1]) : "l"(xd[r]), "l"(w1));
                asm("fma.rn.f32x2 %0, %1, %2, %0;" : "+l"(acc[r][2]) : "l"(xd[r]), "l"(w2));
                asm("fma.rn.f32x2 %0, %1, %2, %0;" : "+l"(acc[r][3]) : "l"(xd[r]), "l"(w3));
            }
        }
    }

    // epilogue
    float bv[8];
#pragma unroll
    for (int c = 0; c < 8; c++) bv[c] = BIAS ? bias[8 * cg + c] : 0.0f;
#pragma unroll
    for (int r = 0; r < 4; r++) {
        long long row = r0 + 4 * rg + r;
        if (row < N_NODES) {
            float* yp = Y + row * NO + 8 * cg;
#pragma unroll
            for (int c = 0; c < 4; c++) {
                float lo = __uint_as_float((unsigned)acc[r][c]);
                float hi = __uint_as_float((unsigned)(acc[r][c] >> 32));
                ((float2*)yp)[c] = make_float2(lo + bv[2 * c], hi + bv[2 * c + 1]);
            }
        }
    }
}

// ---------------- sparse aggregation: one warp per node --------------------
// out[i] = (relu?)( sum_{e: dst=i} w_e * H[src_e] + dinv[i]^2 * H[i] (+ b) )
// 4-way edge unroll: 4 row-gathers in flight per warp.
template <int F, bool RELU, bool BIAS>
__global__ void k_agg(const float* __restrict__ H, const float* __restrict__ b,
                      float* __restrict__ out) {
    int gw   = (blockIdx.x * blockDim.x + threadIdx.x) >> 5;
    int lane = threadIdx.x & 31;
    if (gw >= N_NODES) return;
    int s = g_rowptr[gw], e = g_rowptr[gw + 1];

    if constexpr (F == 128) {
        float4 a0 = make_float4(0.f, 0.f, 0.f, 0.f);
        float4 a1 = make_float4(0.f, 0.f, 0.f, 0.f);
        int j = s;
        for (; j + 4 <= e; j += 4) {
            int2 c0 = __ldg(&g_cw[j]);
            int2 c1 = __ldg(&g_cw[j + 1]);
            int2 c2 = __ldg(&g_cw[j + 2]);
            int2 c3 = __ldg(&g_cw[j + 3]);
            float4 h0 = __ldg(((const float4*)(H + (size_t)c0.x * 128)) + lane);
            float4 h1 = __ldg(((const float4*)(H + (size_t)c1.x * 128)) + lane);
            float4 h2 = __ldg(((const float4*)(H + (size_t)c2.x * 128)) + lane);
            float4 h3 = __ldg(((const float4*)(H + (size_t)c3.x * 128)) + lane);
            float w0 = __int_as_float(c0.y), w1 = __int_as_float(c1.y);
            float w2 = __int_as_float(c2.y), w3 = __int_as_float(c3.y);
            a0.x = fmaf(w0, h0.x, a0.x); a0.y = fmaf(w0, h0.y, a0.y);
            a0.z = fmaf(w0, h0.z, a0.z); a0.w = fmaf(w0, h0.w, a0.w);
            a1.x = fmaf(w1, h1.x, a1.x); a1.y = fmaf(w1, h1.y, a1.y);
            a1.z = fmaf(w1, h1.z, a1.z); a1.w = fmaf(w1, h1.w, a1.w);
            a0.x = fmaf(w2, h2.x, a0.x); a0.y = fmaf(w2, h2.y, a0.y);
            a0.z = fmaf(w2, h2.z, a0.z); a0.w = fmaf(w2, h2.w, a0.w);
            a1.x = fmaf(w3, h3.x, a1.x); a1.y = fmaf(w3, h3.y, a1.y);
            a1.z = fmaf(w3, h3.z, a1.z); a1.w = fmaf(w3, h3.w, a1.w);
        }
        for (; j < e; j++) {
            int2 c0 = __ldg(&g_cw[j]);
            float w0 = __int_as_float(c0.y);
            float4 h0 = __ldg(((const float4*)(H + (size_t)c0.x * 128)) + lane);
            a0.x = fmaf(w0, h0.x, a0.x); a0.y = fmaf(w0, h0.y, a0.y);
            a0.z = fmaf(w0, h0.z, a0.z); a0.w = fmaf(w0, h0.w, a0.w);
        }
        float di = g_dinv[gw];
        float wl = di * di;
        float4 hs = ((const float4*)(H + (size_t)gw * 128))[lane];
        a0.x = fmaf(wl, hs.x, a0.x); a0.y = fmaf(wl, hs.y, a0.y);
        a0.z = fmaf(wl, hs.z, a0.z); a0.w = fmaf(wl, hs.w, a0.w);
        a0.x += a1.x; a0.y += a1.y; a0.z += a1.z; a0.w += a1.w;
        if (BIAS) {
            float4 bb = ((const float4*)b)[lane];
            a0.x += bb.x; a0.y += bb.y; a0.z += bb.z; a0.w += bb.w;
        }
        if (RELU) {
            a0.x = fmaxf(a0.x, 0.f); a0.y = fmaxf(a0.y, 0.f);
            a0.z = fmaxf(a0.z, 0.f); a0.w = fmaxf(a0.w, 0.f);
        }
        ((float4*)(out + (size_t)gw * 128))[lane] = a0;
    } else { // F == 64
        float2 a0 = make_float2(0.f, 0.f);
        float2 a1 = make_float2(0.f, 0.f);
        int j = s;
        for (; j + 4 <= e; j += 4) {
            int2 c0 = __ldg(&g_cw[j]);
            int2 c1 = __ldg(&g_cw[j + 1]);
            int2 c2 = __ldg(&g_cw[j + 2]);
            int2 c3 = __ldg(&g_cw[j + 3]);
            float2 h0 = __ldg(((const float2*)(H + (size_t)c0.x * 64)) + lane);
            float2 h1 = __ldg(((const float2*)(H + (size_t)c1.x * 64)) + lane);
            float2 h2 = __ldg(((const float2*)(H + (size_t)c2.x * 64)) + lane);
            float2 h3 = __ldg(((const float2*)(H + (size_t)c3.x * 64)) + lane);
            float w0 = __int_as_float(c0.y), w1 = __int_as_float(c1.y);
            float w2 = __int_as_float(c2.y), w3 = __int_as_float(c3.y);
            a0.x = fmaf(w0, h0.x, a0.x); a0.y = fmaf(w0, h0.y, a0.y);
            a1.x = fmaf(w1, h1.x, a1.x); a1.y = fmaf(w1, h1.y, a1.y);
            a0.x = fmaf(w2, h2.x, a0.x); a0.y = fmaf(w2, h2.y, a0.y);
            a1.x = fmaf(w3, h3.x, a1.x); a1.y = fmaf(w3, h3.y, a1.y);
        }
        for (; j < e; j++) {
            int2 c0 = __ldg(&g_cw[j]);
            float w0 = __int_as_float(c0.y);
            float2 h0 = __ldg(((const float2*)(H + (size_t)c0.x * 64)) + lane);
            a0.x = fmaf(w0, h0.x, a0.x); a0.y = fmaf(w0, h0.y, a0.y);
        }
        float di = g_dinv[gw];
        float wl = di * di;
        float2 hs = ((const float2*)(H + (size_t)gw * 64))[lane];
        a0.x = fmaf(wl, hs.x, a0.x); a0.y = fmaf(wl, hs.y, a0.y);
        a0.x += a1.x; a0.y += a1.y;
        if (BIAS) {
            float2 bb = ((const float2*)b)[lane];
            a0.x += bb.x; a0.y += bb.y;
        }
        if (RELU) { a0.x = fmaxf(a0.x, 0.f); a0.y = fmaxf(a0.y, 0.f); }
        ((float2*)(out + (size_t)gw * 64))[lane] = a0;
    }
}

// ---------------- launch ----------------------------------------------------
extern "C" void kernel_launch(void* const* d_in, const int* in_sizes, int n_in,
                              void* d_out, int out_size) {
    const float* x  = (const float*)d_in[0];
    const void*  ei = d_in[1];
    const float* W1 = (const float*)d_in[2];
    const float* b1 = (const float*)d_in[3];
    const float* W2 = (const float*)d_in[4];
    const float* b2 = (const float*)d_in[5];
    const float* W3 = (const float*)d_in[6];
    const float* b3 = (const float*)d_in[7];
    float* out = (float*)d_out;

    void *pH = nullptr, *pA = nullptr;
    cudaGetSymbolAddress(&pH, g_H);
    cudaGetSymbolAddress(&pA, g_A);
    float* H = (float*)pH;
    float* A = (float*)pA;

    const int TB = 256;
    int gN = (N_NODES + TB - 1) / TB;
    int gE = (N_EDGES + TB - 1) / TB;
    int aggBlocks = (N_NODES * 32 + TB - 1) / TB;
    int g64  = (N_NODES + 63) / 64;    // blocks for RB=64 gemms
    int g128 = (N_NODES + 127) / 128;  // blocks for RB=128 gemm

    // preprocessing: degree norm + CSR(dst)
    k_zero<<<gN, TB>>>(ei);
    k_hist<<<gE, TB>>>(ei);
    k_scan<<<1, 1024>>>();
    k_fill<<<gE, TB>>>(ei);

    // layer 1: relu(agg(x@W1) + b1)
    k_gemm<128, 128, false><<<g64, 256>>>(x, W1, nullptr, H);
    k_agg<128, true, true><<<aggBlocks, TB>>>(H, b1, A);
    // layer 2: relu(agg(h@W2) + b2)
    k_gemm<128, 64, false><<<g128, 256>>>(A, W2, nullptr, H);
    k_agg<64, true, true><<<aggBlocks, TB>>>(H, b2, A);
    // layer 3 (reordered, agg is linear): out = agg(h) @ W3 + b3
    k_agg<64, false, false><<<aggBlocks, TB>>>(A, nullptr, H);
    k_gemm<64, 128, true><<<g64, 256>>>(H, W3, b3, out);
}